// round 9
// baseline (speedup 1.0000x reference)
#include <cuda_runtime.h>
#include <cuda_bf16.h>
#include <math.h>
#include <stdint.h>

// Problem constants
#define BB 8
#define GG 16
#define NN_ 256
#define DD 768
#define EE 1536
#define SS 128
#define SEQ_ 512
#define TT (BB*GG*NN_)          // 32768 tokens
#define UVW (2*EE+SS)           // 3200

// ---------------- scratch (device globals; no allocations allowed) --------
__device__ float g_xn[(long long)TT*DD];
__device__ float g_uv[(long long)TT*UVW];
__device__ float g_qq[(long long)TT*SS];
__device__ float g_qkk[(long long)TT*SS];
__device__ float g_lq[(long long)TT*SS];
__device__ float g_lk[(long long)TT*SS];
__device__ float g_kv[(long long)BB*SS*EE];
__device__ float g_linv[(long long)TT*EE];
__device__ float g_linkv[(long long)BB*GG*SS*EE];
__device__ float g_linkv2[(long long)BB*GG*SS*EE];
__device__ float g_accb[(long long)TT*EE];
__device__ float g_qkm[(long long)BB*GG*NN_*NN_];
__device__ float g_gated[(long long)TT*EE];
__device__ float g_invf[64];
__device__ int   g_mn[BB*GG];
__device__ int   g_mx[BB*GG];

// ---------------- tf32 helpers -------------------------------------------
__device__ __forceinline__ uint32_t f2tf32(float f) {
    uint32_t u;
    asm("cvt.rna.tf32.f32 %0, %1;" : "=r"(u) : "f"(f));
    return u;
}

__device__ __forceinline__ void mma8(float& c0, float& c1, float& c2, float& c3,
                                     uint32_t a0, uint32_t a1, uint32_t a2, uint32_t a3,
                                     uint32_t b0, uint32_t b1)
{
    asm volatile(
        "mma.sync.aligned.m16n8k8.row.col.f32.tf32.tf32.f32 "
        "{%0,%1,%2,%3}, {%4,%5,%6,%7}, {%8,%9}, {%0,%1,%2,%3};"
        : "+f"(c0), "+f"(c1), "+f"(c2), "+f"(c3)
        : "r"(a0), "r"(a1), "r"(a2), "r"(a3), "r"(b0), "r"(b1));
}

// ---------------- tf32 tensor-core GEMM (single buffer, vec loads) --------
// 128x128 block tile, K-tile 16, 8 warps (2x4), warp tile 64x32.
// opA(m,k) = TA ? A[k*lda+m] : A[m*lda+k];  opB(k,n) = TB ? B[n*ldb+k] : B[k*ldb+n]
// epi: 0 none, 1 bias+silu, 2 bias+residual, 3 gate ((acc+C)*resid -> Cout),
//      4 toeplitz relu^2 (v=relu(acc*alpha + bias[SEQ-1+col-row])^2)
// resid is batch-offset by sR per z.
// REQUIRES: M%128==0, N%128==0, K%16==0, lda/ldb %4==0 (all call sites satisfy).
template<int TA, int TB>
__global__ __launch_bounds__(256, 2)
void tgemm_kernel(const float* __restrict__ A, const float* __restrict__ B,
                  float* __restrict__ C, float* __restrict__ Cout,
                  int M, int N, int K, int lda, int ldb, int ldc,
                  long long sA, long long sB, long long sC,
                  float alpha, int accumulate, int epi,
                  const float* __restrict__ bias,
                  const float* __restrict__ resid, int ldr, long long sR)
{
    // stride-20 padded smem: conflict-free tf32 fragment loads
    __shared__ __align__(16) uint32_t As[128 * 20];
    __shared__ __align__(16) uint32_t Bs[128 * 20];

    int z = blockIdx.z;
    A += (long long)z * sA; B += (long long)z * sB;
    C += (long long)z * sC; Cout += (long long)z * sC;
    if (resid) resid += (long long)z * sR;
    int tid  = threadIdx.x;
    int lane = tid & 31;
    int warp = tid >> 5;
    int wm = (warp >> 2) * 64;
    int wn = (warp & 3) * 32;
    int bm = blockIdx.y * 128;
    int bn = blockIdx.x * 128;
    int g = lane >> 2, t = lane & 3;

    float acc[4][4][4];
#pragma unroll
    for (int mf = 0; mf < 4; mf++)
#pragma unroll
        for (int nf = 0; nf < 4; nf++)
#pragma unroll
            for (int i = 0; i < 4; i++) acc[mf][nf][i] = 0.f;

    for (int k0 = 0; k0 < K; k0 += 16) {
        // ---- global -> smem, float4 loads, immediate stores ----
#pragma unroll
        for (int l = 0; l < 2; l++) {
            int idx = l * 1024 + tid * 4;
            float4 r;
            if (TA) {
                int k = idx >> 7, m = idx & 127;
                r = *(const float4*)&A[(long long)(k0 + k) * lda + bm + m];
                As[(m+0)*20+k] = f2tf32(r.x); As[(m+1)*20+k] = f2tf32(r.y);
                As[(m+2)*20+k] = f2tf32(r.z); As[(m+3)*20+k] = f2tf32(r.w);
            } else {
                int m = idx >> 4, k = idx & 15;
                r = *(const float4*)&A[(long long)(bm + m) * lda + k0 + k];
                *(uint4*)&As[m*20+k] =
                    make_uint4(f2tf32(r.x), f2tf32(r.y), f2tf32(r.z), f2tf32(r.w));
            }
        }
#pragma unroll
        for (int l = 0; l < 2; l++) {
            int idx = l * 1024 + tid * 4;
            float4 r;
            if (TB) {
                int n = idx >> 4, k = idx & 15;
                r = *(const float4*)&B[(long long)(bn + n) * ldb + k0 + k];
                *(uint4*)&Bs[n*20+k] =
                    make_uint4(f2tf32(r.x), f2tf32(r.y), f2tf32(r.z), f2tf32(r.w));
            } else {
                int k = idx >> 7, n = idx & 127;
                r = *(const float4*)&B[(long long)(k0 + k) * ldb + bn + n];
                Bs[(n+0)*20+k] = f2tf32(r.x); Bs[(n+1)*20+k] = f2tf32(r.y);
                Bs[(n+2)*20+k] = f2tf32(r.z); Bs[(n+3)*20+k] = f2tf32(r.w);
            }
        }
        __syncthreads();

        // ---- two k=8 steps of mma ----
#pragma unroll
        for (int ks = 0; ks < 2; ks++) {
            int kk = ks * 8;
            uint32_t af[4][4], bf[4][2];
#pragma unroll
            for (int mf = 0; mf < 4; mf++) {
                int r = wm + mf * 16 + g;
                af[mf][0] = As[r * 20 + kk + t];
                af[mf][1] = As[(r + 8) * 20 + kk + t];
                af[mf][2] = As[r * 20 + kk + t + 4];
                af[mf][3] = As[(r + 8) * 20 + kk + t + 4];
            }
#pragma unroll
            for (int nf = 0; nf < 4; nf++) {
                int cn = wn + nf * 8 + g;
                bf[nf][0] = Bs[cn * 20 + kk + t];
                bf[nf][1] = Bs[cn * 20 + kk + t + 4];
            }
#pragma unroll
            for (int mf = 0; mf < 4; mf++)
#pragma unroll
                for (int nf = 0; nf < 4; nf++)
                    mma8(acc[mf][nf][0], acc[mf][nf][1], acc[mf][nf][2], acc[mf][nf][3],
                         af[mf][0], af[mf][1], af[mf][2], af[mf][3],
                         bf[nf][0], bf[nf][1]);
        }
        __syncthreads();
    }

    // ---- epilogue ----
#pragma unroll
    for (int mf = 0; mf < 4; mf++) {
#pragma unroll
        for (int nf = 0; nf < 4; nf++) {
#pragma unroll
            for (int i = 0; i < 4; i++) {
                int row = bm + wm + mf * 16 + g + ((i >= 2) ? 8 : 0);
                int col = bn + wn + nf * 8 + 2 * t + (i & 1);
                float v = acc[mf][nf][i] * alpha;
                long long off = (long long)row * ldc + col;
                if (accumulate) v += C[off];
                if (epi == 1) {
                    v += bias[col];
                    v = v / (1.f + expf(-v));          // silu
                } else if (epi == 2) {
                    v += bias[col] + resid[(long long)row * ldr + col];
                } else if (epi == 3) {
                    v *= resid[(long long)row * ldr + col];
                } else if (epi == 4) {
                    v += bias[SEQ_ - 1 + col - row];
                    v = fmaxf(v, 0.f);
                    v *= v;
                }
                Cout[off] = v;
            }
        }
    }
}

// ---------------- layernorm --------------------------------------------
__global__ void ln_kernel(const float* __restrict__ x, const float* __restrict__ w,
                          const float* __restrict__ b, float* __restrict__ y)
{
    int t = blockIdx.x;
    const float* row = x + (long long)t * DD;
    float* outp = y + (long long)t * DD;
    __shared__ float red[8];
    __shared__ float s_mu, s_rstd;
    int tid = threadIdx.x;          // 256
    float s = 0.f;
    for (int i = tid; i < DD; i += 256) s += row[i];
#pragma unroll
    for (int o = 16; o > 0; o >>= 1) s += __shfl_xor_sync(0xffffffffu, s, o);
    if ((tid & 31) == 0) red[tid >> 5] = s;
    __syncthreads();
    if (tid == 0) {
        float tot = 0.f;
        for (int i = 0; i < 8; i++) tot += red[i];
        s_mu = tot / (float)DD;
    }
    __syncthreads();
    float mu = s_mu;
    float vs = 0.f;
    for (int i = tid; i < DD; i += 256) { float d = row[i] - mu; vs += d * d; }
#pragma unroll
    for (int o = 16; o > 0; o >>= 1) vs += __shfl_xor_sync(0xffffffffu, vs, o);
    if ((tid & 31) == 0) red[tid >> 5] = vs;
    __syncthreads();
    if (tid == 0) {
        float tot = 0.f;
        for (int i = 0; i < 8; i++) tot += red[i];
        s_rstd = rsqrtf(tot / (float)DD + 1e-5f);
    }
    __syncthreads();
    float rstd = s_rstd;
    for (int i = tid; i < DD; i += 256)
        outp[i] = (row[i] - mu) * rstd * w[i] + b[i];
}

// ---------------- inv_freq (double precision, correctly rounded fp32) -----
__global__ void invf_kernel(float* g)
{
    int j = threadIdx.x;
    if (j < 64) g[j] = (float)exp(log(10000.0) * ((double)j / 64.0));
}

// ---------------- affine (gamma/beta) + RoPE -> 4 components --------------
__global__ void rope_kernel(const float* __restrict__ uv, const float* __restrict__ gamma,
                            const float* __restrict__ beta, const float* __restrict__ invf,
                            float* __restrict__ qq, float* __restrict__ qk,
                            float* __restrict__ lq, float* __restrict__ lk)
{
    int t = blockIdx.x;             // token
    int j = threadIdx.x;            // 0..63
    int g = (t >> 8) & (GG - 1);
    int n = t & (NN_ - 1);
    float p = (float)((g << 8) + n);
    float arg = p * invf[j];
    float sn, cs;
    sincosf(arg, &sn, &cs);
    const float* zp = uv + (long long)t * UVW + 2 * EE;
    float z1 = zp[j], z2 = zp[j + 64];
    float* outs[4] = {qq, qk, lq, lk};
#pragma unroll
    for (int i = 0; i < 4; i++) {
        float a1 = z1 * gamma[i * SS + j]      + beta[i * SS + j];
        float a2 = z2 * gamma[i * SS + 64 + j] + beta[i * SS + 64 + j];
        float* o = outs[i] + (long long)t * SS;
        o[j]      = a1 * cs - a2 * sn;
        o[j + 64] = a2 * cs + a1 * sn;
    }
}

// ---------------- segment min/max per (b,g) -------------------------------
__global__ void minmax_kernel(const int* __restrict__ seg, int* __restrict__ mn,
                              int* __restrict__ mx)
{
    int bg = blockIdx.x;
    int tid = threadIdx.x;          // 256
    int v = seg[(long long)bg * NN_ + tid];
    int a = v, b = v;
#pragma unroll
    for (int o = 16; o > 0; o >>= 1) {
        a = min(a, __shfl_xor_sync(0xffffffffu, a, o));
        b = max(b, __shfl_xor_sync(0xffffffffu, b, o));
    }
    __shared__ int smn[8], smx[8];
    if ((tid & 31) == 0) { smn[tid >> 5] = a; smx[tid >> 5] = b; }
    __syncthreads();
    if (tid == 0) {
        int aa = smn[0], bb = smx[0];
        for (int i = 1; i < 8; i++) { aa = min(aa, smn[i]); bb = max(bb, smx[i]); }
        mn[bg] = aa; mx[bg] = bb;
    }
}

// ---------------- group mixing: read-once, accumulate 16 outputs ----------
__global__ void mix_kernel(const float* __restrict__ lin_kv, const int* __restrict__ mn,
                           const int* __restrict__ mx, float* __restrict__ outp)
{
    const long long SE = (long long)SS * EE;   // 196608
    int b = blockIdx.y;
    int tid = threadIdx.x;
    __shared__ float w[16][16];
    {
        int g = tid >> 4, h = tid & 15;
        if (tid < 256) {
            int mng = mn[b * 16 + g], mxg = mx[b * 16 + g];
            int ov = (mng <= mx[b * 16 + h] && mxg >= mn[b * 16 + h]) ? 1 : 0;
            w[g][h] = (float)ov;
        }
    }
    __syncthreads();
    if (tid < 16) {
        float s = 0.f;
        for (int h = 0; h < 16; h++) s += w[tid][h];
        float inv = 1.f / s;
        for (int h = 0; h < 16; h++) w[tid][h] *= inv;
    }
    __syncthreads();

    long long idx = (long long)blockIdx.x * 256 + tid;     // 0..SE
    const float* src = lin_kv + (long long)b * 16 * SE + idx;
    float o[16];
#pragma unroll
    for (int g = 0; g < 16; g++) o[g] = 0.f;
#pragma unroll
    for (int h = 0; h < 16; h++) {
        float v = src[(long long)h * SE];
#pragma unroll
        for (int g = 0; g < 16; g++) o[g] = fmaf(w[g][h], v, o[g]);
    }
    float* dst = outp + (long long)b * 16 * SE + idx;
#pragma unroll
    for (int g = 0; g < 16; g++) dst[(long long)g * SE] = o[g];
}

// ---------------- launch ---------------------------------------------------
extern "C" void kernel_launch(void* const* d_in, const int* in_sizes, int n_in,
                              void* d_out, int out_size)
{
    const float* inputs = (const float*)d_in[0];
    const int*   seg    = (const int*)  d_in[1];
    const float* ln_w   = (const float*)d_in[2];
    const float* ln_b   = (const float*)d_in[3];
    const float* W1     = (const float*)d_in[4];
    const float* b1     = (const float*)d_in[5];
    const float* gamma  = (const float*)d_in[6];
    const float* beta   = (const float*)d_in[7];
    const float* W2     = (const float*)d_in[8];
    const float* b2     = (const float*)d_in[9];
    const float* w_rel  = (const float*)d_in[10];
    float* outp = (float*)d_out;

    float *xn, *uv, *qq, *qkk, *lq, *lk, *kv, *linv, *linkv, *linkv2, *accb, *qkm, *gated, *invf;
    int *mn, *mx;
    cudaGetSymbolAddress((void**)&xn,    g_xn);
    cudaGetSymbolAddress((void**)&uv,    g_uv);
    cudaGetSymbolAddress((void**)&qq,    g_qq);
    cudaGetSymbolAddress((void**)&qkk,   g_qkk);
    cudaGetSymbolAddress((void**)&lq,    g_lq);
    cudaGetSymbolAddress((void**)&lk,    g_lk);
    cudaGetSymbolAddress((void**)&kv,    g_kv);
    cudaGetSymbolAddress((void**)&linv,  g_linv);
    cudaGetSymbolAddress((void**)&linkv, g_linkv);
    cudaGetSymbolAddress((void**)&linkv2,g_linkv2);
    cudaGetSymbolAddress((void**)&accb,  g_accb);
    cudaGetSymbolAddress((void**)&qkm,   g_qkm);
    cudaGetSymbolAddress((void**)&gated, g_gated);
    cudaGetSymbolAddress((void**)&invf,  g_invf);
    cudaGetSymbolAddress((void**)&mn,    g_mn);
    cudaGetSymbolAddress((void**)&mx,    g_mx);

    // 1. LayerNorm
    ln_kernel<<<TT, 256>>>(inputs, ln_w, ln_b, xn);

    // 2. uv = silu(xn @ W1 + b1)   [32768,768]x[768,3200]
    tgemm_kernel<0,0><<<dim3(25, 256, 1), 256>>>(
        xn, W1, uv, uv, TT, UVW, DD, DD, UVW, UVW, 0, 0, 0,
        1.f, 0, 1, b1, nullptr, 0, 0);

    // 3. inv_freq + RoPE components
    invf_kernel<<<1, 64>>>(invf);
    rope_kernel<<<TT, 64>>>(uv, gamma, beta, invf, qq, qkk, lq, lk);

    // 4. kv[b] = lin_k[b]^T @ v[b]   per b: [4096,128]^T x [4096,1536]
    tgemm_kernel<1,0><<<dim3(12, 1, BB), 256>>>(
        lk, uv + EE, kv, kv, SS, EE, GG*NN_, SS, UVW, EE,
        (long long)GG*NN_*SS, (long long)GG*NN_*UVW, (long long)SS*EE,
        1.f, 0, 0, nullptr, nullptr, 0, 0);

    // 5. lin_v[b] = lin_q[b] @ kv[b]   per b: [4096,128] x [128,1536]
    tgemm_kernel<0,0><<<dim3(12, 32, BB), 256>>>(
        lq, kv, linv, linv, GG*NN_, EE, SS, SS, EE, EE,
        (long long)GG*NN_*SS, (long long)SS*EE, (long long)GG*NN_*EE,
        1.f, 0, 0, nullptr, nullptr, 0, 0);

    // 6. lin_kv[bg] = lin_k[bg]^T @ lin_v[bg] / n   per bg: [256,128]^T x [256,1536]
    tgemm_kernel<1,0><<<dim3(12, 1, BB*GG), 256>>>(
        lk, linv, linkv, linkv, SS, EE, NN_, SS, EE, EE,
        (long long)NN_*SS, (long long)NN_*EE, (long long)SS*EE,
        1.f / (float)NN_, 0, 0, nullptr, nullptr, 0, 0);

    // 7. segment mask mixing
    minmax_kernel<<<BB*GG, 256>>>(seg, mn, mx);
    mix_kernel<<<dim3((SS*EE)/256, BB), 256>>>(linkv, mn, mx, linkv2);

    // 8. linear[bg] = lin_q[bg] @ lin_kv2[bg]   per bg: [256,128] x [128,1536]
    tgemm_kernel<0,0><<<dim3(12, 2, BB*GG), 256>>>(
        lq, linkv2, accb, accb, NN_, EE, SS, SS, EE, EE,
        (long long)NN_*SS, (long long)SS*EE, (long long)NN_*EE,
        1.f, 0, 0, nullptr, nullptr, 0, 0);

    // 9. qk[bg] = relu(quad_q@quad_k^T/n + toeplitz)^2 (fused epi=4)
    tgemm_kernel<0,1><<<dim3(2, 2, BB*GG), 256>>>(
        qq, qkk, qkm, qkm, NN_, NN_, SS, SS, SS, NN_,
        (long long)NN_*SS, (long long)NN_*SS, (long long)NN_*NN_,
        1.f / (float)NN_, 0, 4, w_rel, nullptr, 0, 0);

    // 10+11+12. gated = u * (kernel[bg] @ v[bg] + linear)  (fused epi=3)
    // resid = u part of uv, batch stride NN_*UVW
    tgemm_kernel<0,0><<<dim3(12, 2, BB*GG), 256>>>(
        qkm, uv + EE, accb, gated, NN_, EE, NN_, NN_, UVW, EE,
        (long long)NN_*NN_, (long long)NN_*UVW, (long long)NN_*EE,
        1.f, 1, 3, nullptr, uv, UVW, (long long)NN_*UVW);

    // 13. out = gated @ W2 + b2 + shortcut   [32768,1536]x[1536,768]
    tgemm_kernel<0,0><<<dim3(6, 256, 1), 256>>>(
        gated, W2, outp, outp, TT, DD, EE, EE, DD, DD, 0, 0, 0,
        1.f, 0, 2, b2, inputs, DD, 0);
}

// round 12
// speedup vs baseline: 2.0611x; 2.0611x over previous
#include <cuda_runtime.h>
#include <cuda_bf16.h>
#include <cuda_fp16.h>
#include <math.h>
#include <stdint.h>

// Problem constants
#define BB 8
#define GG 16
#define NN_ 256
#define DD 768
#define EE 1536
#define SS 128
#define SEQ_ 512
#define TT (BB*GG*NN_)          // 32768 tokens
#define UVW (2*EE+SS)           // 3200

// ---------------- scratch (device globals; no allocations allowed) --------
__device__ float g_xn[(long long)TT*DD];
__device__ float g_uv[(long long)TT*UVW];
__device__ float g_qq[(long long)TT*SS];
__device__ float g_qkk[(long long)TT*SS];
__device__ float g_lq[(long long)TT*SS];
__device__ float g_lk[(long long)TT*SS];
__device__ float g_kv[(long long)BB*SS*EE];
__device__ float g_linv[(long long)TT*EE];
__device__ float g_linkv[(long long)BB*GG*SS*EE];
__device__ float g_linkv2[(long long)BB*GG*SS*EE];
__device__ float g_accb[(long long)TT*EE];
__device__ float g_qkm[(long long)BB*GG*NN_*NN_];
__device__ float g_gated[(long long)TT*EE];
__device__ float g_invf[64];
__device__ int   g_mn[BB*GG];
__device__ int   g_mx[BB*GG];

// ---------------- fp16 helpers -------------------------------------------
__device__ __forceinline__ uint32_t f2h2(float lo, float hi) {
    __half2 h = __floats2half2_rn(lo, hi);
    return *reinterpret_cast<uint32_t*>(&h);
}

__device__ __forceinline__ void mma16(float& c0, float& c1, float& c2, float& c3,
                                      uint32_t a0, uint32_t a1, uint32_t a2, uint32_t a3,
                                      uint32_t b0, uint32_t b1)
{
    asm volatile(
        "mma.sync.aligned.m16n8k16.row.col.f32.f16.f16.f32 "
        "{%0,%1,%2,%3}, {%4,%5,%6,%7}, {%8,%9}, {%0,%1,%2,%3};"
        : "+f"(c0), "+f"(c1), "+f"(c2), "+f"(c3)
        : "r"(a0), "r"(a1), "r"(a2), "r"(a3), "r"(b0), "r"(b1));
}

// ---------------- fp16 tensor-core GEMM (fp32 accum) ----------------------
// 128x128 block tile, K-tile 32 (fp16), 8 warps (2x4), warp tile 64x32.
// Smem: [row][20 half2-words], stride 20 words (40 halves) -> conflict-free
// fragment loads (same word pattern as the verified tf32 kernel).
// opA(m,k) = TA ? A[k*lda+m] : A[m*lda+k];  opB(k,n) = TB ? B[n*ldb+k] : B[k*ldb+n]
// epi: 0 none, 1 bias+silu, 2 bias+residual, 3 gate ((acc+C)*resid -> Cout),
//      4 toeplitz relu^2 (v=relu(acc*alpha + bias[SEQ-1+col-row])^2)
// resid is batch-offset by sR per z.
// REQUIRES: M%128==0, N%128==0, K%32==0, lda/ldb%4==0 (all call sites satisfy).
template<int TA, int TB>
__global__ __launch_bounds__(256, 2)
void hgemm_kernel(const float* __restrict__ A, const float* __restrict__ B,
                  float* __restrict__ C, float* __restrict__ Cout,
                  int M, int N, int K, int lda, int ldb, int ldc,
                  long long sA, long long sB, long long sC,
                  float alpha, int accumulate, int epi,
                  const float* __restrict__ bias,
                  const float* __restrict__ resid, int ldr, long long sR)
{
    __shared__ __align__(16) uint32_t As[128 * 20];   // half2 words
    __shared__ __align__(16) uint32_t Bs[128 * 20];

    int z = blockIdx.z;
    A += (long long)z * sA; B += (long long)z * sB;
    C += (long long)z * sC; Cout += (long long)z * sC;
    if (resid) resid += (long long)z * sR;
    int tid  = threadIdx.x;
    int lane = tid & 31;
    int warp = tid >> 5;
    int wm = (warp >> 2) * 64;
    int wn = (warp & 3) * 32;
    int bm = blockIdx.y * 128;
    int bn = blockIdx.x * 128;
    int g = lane >> 2, t = lane & 3;

    float acc[4][4][4];
#pragma unroll
    for (int mf = 0; mf < 4; mf++)
#pragma unroll
        for (int nf = 0; nf < 4; nf++)
#pragma unroll
            for (int i = 0; i < 4; i++) acc[mf][nf][i] = 0.f;

    for (int k0 = 0; k0 < K; k0 += 32) {
        // ---- A: global -> smem half2 ----
        if (TA == 0) {
            // row-major: float4 along k, 8B STS (2-way max conflict)
#pragma unroll
            for (int l = 0; l < 4; l++) {
                int idx = l * 1024 + tid * 4;          // 0..4095
                int m = idx >> 5, kf = idx & 31;
                float4 r = *(const float4*)&A[(long long)(bm + m) * lda + k0 + kf];
                *(uint2*)&As[m * 20 + (kf >> 1)] =
                    make_uint2(f2h2(r.x, r.y), f2h2(r.z, r.w));
            }
        } else {
            // k-major: two scalar loads along k (coalesced over m), 4B STS (4-way max)
#pragma unroll
            for (int l = 0; l < 8; l++) {
                int widx = l * 256 + tid;              // 0..2047
                int m = widx & 127, wk = widx >> 7;    // wk 0..15
                float x = A[(long long)(k0 + 2 * wk)     * lda + bm + m];
                float y = A[(long long)(k0 + 2 * wk + 1) * lda + bm + m];
                As[m * 20 + wk] = f2h2(x, y);
            }
        }
        // ---- B: global -> smem half2 ----
        if (TB == 1) {
            // n-major rows of k: float4 along k, 8B STS
#pragma unroll
            for (int l = 0; l < 4; l++) {
                int idx = l * 1024 + tid * 4;
                int n = idx >> 5, kf = idx & 31;
                float4 r = *(const float4*)&B[(long long)(bn + n) * ldb + k0 + kf];
                *(uint2*)&Bs[n * 20 + (kf >> 1)] =
                    make_uint2(f2h2(r.x, r.y), f2h2(r.z, r.w));
            }
        } else {
            // k-major: two scalar loads along k (coalesced over n), 4B STS
#pragma unroll
            for (int l = 0; l < 8; l++) {
                int widx = l * 256 + tid;
                int n = widx & 127, wk = widx >> 7;
                float x = B[(long long)(k0 + 2 * wk)     * ldb + bn + n];
                float y = B[(long long)(k0 + 2 * wk + 1) * ldb + bn + n];
                Bs[n * 20 + wk] = f2h2(x, y);
            }
        }
        __syncthreads();

        // ---- two k=16 steps of mma ----
#pragma unroll
        for (int ks = 0; ks < 2; ks++) {
            int kw = ks * 8;                            // half2-word offset
            uint32_t af[4][4], bf[4][2];
#pragma unroll
            for (int mf = 0; mf < 4; mf++) {
                int r = wm + mf * 16 + g;
                af[mf][0] = As[r * 20 + kw + t];
                af[mf][1] = As[(r + 8) * 20 + kw + t];
                af[mf][2] = As[r * 20 + kw + t + 4];
                af[mf][3] = As[(r + 8) * 20 + kw + t + 4];
            }
#pragma unroll
            for (int nf = 0; nf < 4; nf++) {
                int cn = wn + nf * 8 + g;
                bf[nf][0] = Bs[cn * 20 + kw + t];
                bf[nf][1] = Bs[cn * 20 + kw + t + 4];
            }
#pragma unroll
            for (int mf = 0; mf < 4; mf++)
#pragma unroll
                for (int nf = 0; nf < 4; nf++)
                    mma16(acc[mf][nf][0], acc[mf][nf][1], acc[mf][nf][2], acc[mf][nf][3],
                          af[mf][0], af[mf][1], af[mf][2], af[mf][3],
                          bf[nf][0], bf[nf][1]);
        }
        __syncthreads();
    }

    // ---- epilogue ----
#pragma unroll
    for (int mf = 0; mf < 4; mf++) {
#pragma unroll
        for (int nf = 0; nf < 4; nf++) {
#pragma unroll
            for (int i = 0; i < 4; i++) {
                int row = bm + wm + mf * 16 + g + ((i >= 2) ? 8 : 0);
                int col = bn + wn + nf * 8 + 2 * t + (i & 1);
                float v = acc[mf][nf][i] * alpha;
                long long off = (long long)row * ldc + col;
                if (accumulate) v += C[off];
                if (epi == 1) {
                    v += bias[col];
                    v = v / (1.f + expf(-v));          // silu
                } else if (epi == 2) {
                    v += bias[col] + resid[(long long)row * ldr + col];
                } else if (epi == 3) {
                    v *= resid[(long long)row * ldr + col];
                } else if (epi == 4) {
                    v += bias[SEQ_ - 1 + col - row];
                    v = fmaxf(v, 0.f);
                    v *= v;
                }
                Cout[off] = v;
            }
        }
    }
}

// ---------------- layernorm --------------------------------------------
__global__ void ln_kernel(const float* __restrict__ x, const float* __restrict__ w,
                          const float* __restrict__ b, float* __restrict__ y)
{
    int t = blockIdx.x;
    const float* row = x + (long long)t * DD;
    float* outp = y + (long long)t * DD;
    __shared__ float red[8];
    __shared__ float s_mu, s_rstd;
    int tid = threadIdx.x;          // 256
    float s = 0.f;
    for (int i = tid; i < DD; i += 256) s += row[i];
#pragma unroll
    for (int o = 16; o > 0; o >>= 1) s += __shfl_xor_sync(0xffffffffu, s, o);
    if ((tid & 31) == 0) red[tid >> 5] = s;
    __syncthreads();
    if (tid == 0) {
        float tot = 0.f;
        for (int i = 0; i < 8; i++) tot += red[i];
        s_mu = tot / (float)DD;
    }
    __syncthreads();
    float mu = s_mu;
    float vs = 0.f;
    for (int i = tid; i < DD; i += 256) { float d = row[i] - mu; vs += d * d; }
#pragma unroll
    for (int o = 16; o > 0; o >>= 1) vs += __shfl_xor_sync(0xffffffffu, vs, o);
    if ((tid & 31) == 0) red[tid >> 5] = vs;
    __syncthreads();
    if (tid == 0) {
        float tot = 0.f;
        for (int i = 0; i < 8; i++) tot += red[i];
        s_rstd = rsqrtf(tot / (float)DD + 1e-5f);
    }
    __syncthreads();
    float rstd = s_rstd;
    for (int i = tid; i < DD; i += 256)
        outp[i] = (row[i] - mu) * rstd * w[i] + b[i];
}

// ---------------- inv_freq (double precision, correctly rounded fp32) -----
__global__ void invf_kernel(float* g)
{
    int j = threadIdx.x;
    if (j < 64) g[j] = (float)exp(log(10000.0) * ((double)j / 64.0));
}

// ---------------- affine (gamma/beta) + RoPE -> 4 components --------------
__global__ void rope_kernel(const float* __restrict__ uv, const float* __restrict__ gamma,
                            const float* __restrict__ beta, const float* __restrict__ invf,
                            float* __restrict__ qq, float* __restrict__ qk,
                            float* __restrict__ lq, float* __restrict__ lk)
{
    int t = blockIdx.x;             // token
    int j = threadIdx.x;            // 0..63
    int g = (t >> 8) & (GG - 1);
    int n = t & (NN_ - 1);
    float p = (float)((g << 8) + n);
    float arg = p * invf[j];
    float sn, cs;
    sincosf(arg, &sn, &cs);
    const float* zp = uv + (long long)t * UVW + 2 * EE;
    float z1 = zp[j], z2 = zp[j + 64];
    float* outs[4] = {qq, qk, lq, lk};
#pragma unroll
    for (int i = 0; i < 4; i++) {
        float a1 = z1 * gamma[i * SS + j]      + beta[i * SS + j];
        float a2 = z2 * gamma[i * SS + 64 + j] + beta[i * SS + 64 + j];
        float* o = outs[i] + (long long)t * SS;
        o[j]      = a1 * cs - a2 * sn;
        o[j + 64] = a2 * cs + a1 * sn;
    }
}

// ---------------- segment min/max per (b,g) -------------------------------
__global__ void minmax_kernel(const int* __restrict__ seg, int* __restrict__ mn,
                              int* __restrict__ mx)
{
    int bg = blockIdx.x;
    int tid = threadIdx.x;          // 256
    int v = seg[(long long)bg * NN_ + tid];
    int a = v, b = v;
#pragma unroll
    for (int o = 16; o > 0; o >>= 1) {
        a = min(a, __shfl_xor_sync(0xffffffffu, a, o));
        b = max(b, __shfl_xor_sync(0xffffffffu, b, o));
    }
    __shared__ int smn[8], smx[8];
    if ((tid & 31) == 0) { smn[tid >> 5] = a; smx[tid >> 5] = b; }
    __syncthreads();
    if (tid == 0) {
        int aa = smn[0], bb = smx[0];
        for (int i = 1; i < 8; i++) { aa = min(aa, smn[i]); bb = max(bb, smx[i]); }
        mn[bg] = aa; mx[bg] = bb;
    }
}

// ---------------- group mixing: read-once, accumulate 16 outputs ----------
__global__ void mix_kernel(const float* __restrict__ lin_kv, const int* __restrict__ mn,
                           const int* __restrict__ mx, float* __restrict__ outp)
{
    const long long SE = (long long)SS * EE;   // 196608
    int b = blockIdx.y;
    int tid = threadIdx.x;
    __shared__ float w[16][16];
    {
        int g = tid >> 4, h = tid & 15;
        if (tid < 256) {
            int mng = mn[b * 16 + g], mxg = mx[b * 16 + g];
            int ov = (mng <= mx[b * 16 + h] && mxg >= mn[b * 16 + h]) ? 1 : 0;
            w[g][h] = (float)ov;
        }
    }
    __syncthreads();
    if (tid < 16) {
        float s = 0.f;
        for (int h = 0; h < 16; h++) s += w[tid][h];
        float inv = 1.f / s;
        for (int h = 0; h < 16; h++) w[tid][h] *= inv;
    }
    __syncthreads();

    long long idx = (long long)blockIdx.x * 256 + tid;     // 0..SE
    const float* src = lin_kv + (long long)b * 16 * SE + idx;
    float o[16];
#pragma unroll
    for (int g = 0; g < 16; g++) o[g] = 0.f;
#pragma unroll
    for (int h = 0; h < 16; h++) {
        float v = src[(long long)h * SE];
#pragma unroll
        for (int g = 0; g < 16; g++) o[g] = fmaf(w[g][h], v, o[g]);
    }
    float* dst = outp + (long long)b * 16 * SE + idx;
#pragma unroll
    for (int g = 0; g < 16; g++) dst[(long long)g * SE] = o[g];
}

// ---------------- launch ---------------------------------------------------
extern "C" void kernel_launch(void* const* d_in, const int* in_sizes, int n_in,
                              void* d_out, int out_size)
{
    const float* inputs = (const float*)d_in[0];
    const int*   seg    = (const int*)  d_in[1];
    const float* ln_w   = (const float*)d_in[2];
    const float* ln_b   = (const float*)d_in[3];
    const float* W1     = (const float*)d_in[4];
    const float* b1     = (const float*)d_in[5];
    const float* gamma  = (const float*)d_in[6];
    const float* beta   = (const float*)d_in[7];
    const float* W2     = (const float*)d_in[8];
    const float* b2     = (const float*)d_in[9];
    const float* w_rel  = (const float*)d_in[10];
    float* outp = (float*)d_out;

    float *xn, *uv, *qq, *qkk, *lq, *lk, *kv, *linv, *linkv, *linkv2, *accb, *qkm, *gated, *invf;
    int *mn, *mx;
    cudaGetSymbolAddress((void**)&xn,    g_xn);
    cudaGetSymbolAddress((void**)&uv,    g_uv);
    cudaGetSymbolAddress((void**)&qq,    g_qq);
    cudaGetSymbolAddress((void**)&qkk,   g_qkk);
    cudaGetSymbolAddress((void**)&lq,    g_lq);
    cudaGetSymbolAddress((void**)&lk,    g_lk);
    cudaGetSymbolAddress((void**)&kv,    g_kv);
    cudaGetSymbolAddress((void**)&linv,  g_linv);
    cudaGetSymbolAddress((void**)&linkv, g_linkv);
    cudaGetSymbolAddress((void**)&linkv2,g_linkv2);
    cudaGetSymbolAddress((void**)&accb,  g_accb);
    cudaGetSymbolAddress((void**)&qkm,   g_qkm);
    cudaGetSymbolAddress((void**)&gated, g_gated);
    cudaGetSymbolAddress((void**)&invf,  g_invf);
    cudaGetSymbolAddress((void**)&mn,    g_mn);
    cudaGetSymbolAddress((void**)&mx,    g_mx);

    // 1. LayerNorm
    ln_kernel<<<TT, 256>>>(inputs, ln_w, ln_b, xn);

    // 2. uv = silu(xn @ W1 + b1)   [32768,768]x[768,3200]
    hgemm_kernel<0,0><<<dim3(25, 256, 1), 256>>>(
        xn, W1, uv, uv, TT, UVW, DD, DD, UVW, UVW, 0, 0, 0,
        1.f, 0, 1, b1, nullptr, 0, 0);

    // 3. inv_freq + RoPE components
    invf_kernel<<<1, 64>>>(invf);
    rope_kernel<<<TT, 64>>>(uv, gamma, beta, invf, qq, qkk, lq, lk);

    // 4. kv[b] = lin_k[b]^T @ v[b]   per b: [4096,128]^T x [4096,1536]
    hgemm_kernel<1,0><<<dim3(12, 1, BB), 256>>>(
        lk, uv + EE, kv, kv, SS, EE, GG*NN_, SS, UVW, EE,
        (long long)GG*NN_*SS, (long long)GG*NN_*UVW, (long long)SS*EE,
        1.f, 0, 0, nullptr, nullptr, 0, 0);

    // 5. lin_v[b] = lin_q[b] @ kv[b]   per b: [4096,128] x [128,1536]
    hgemm_kernel<0,0><<<dim3(12, 32, BB), 256>>>(
        lq, kv, linv, linv, GG*NN_, EE, SS, SS, EE, EE,
        (long long)GG*NN_*SS, (long long)SS*EE, (long long)GG*NN_*EE,
        1.f, 0, 0, nullptr, nullptr, 0, 0);

    // 6. lin_kv[bg] = lin_k[bg]^T @ lin_v[bg] / n   per bg: [256,128]^T x [256,1536]
    hgemm_kernel<1,0><<<dim3(12, 1, BB*GG), 256>>>(
        lk, linv, linkv, linkv, SS, EE, NN_, SS, EE, EE,
        (long long)NN_*SS, (long long)NN_*EE, (long long)SS*EE,
        1.f / (float)NN_, 0, 0, nullptr, nullptr, 0, 0);

    // 7. segment mask mixing
    minmax_kernel<<<BB*GG, 256>>>(seg, mn, mx);
    mix_kernel<<<dim3((SS*EE)/256, BB), 256>>>(linkv, mn, mx, linkv2);

    // 8. linear[bg] = lin_q[bg] @ lin_kv2[bg]   per bg: [256,128] x [128,1536]
    hgemm_kernel<0,0><<<dim3(12, 2, BB*GG), 256>>>(
        lq, linkv2, accb, accb, NN_, EE, SS, SS, EE, EE,
        (long long)NN_*SS, (long long)SS*EE, (long long)NN_*EE,
        1.f, 0, 0, nullptr, nullptr, 0, 0);

    // 9. qk[bg] = relu(quad_q@quad_k^T/n + toeplitz)^2 (fused epi=4)
    hgemm_kernel<0,1><<<dim3(2, 2, BB*GG), 256>>>(
        qq, qkk, qkm, qkm, NN_, NN_, SS, SS, SS, NN_,
        (long long)NN_*SS, (long long)NN_*SS, (long long)NN_*NN_,
        1.f / (float)NN_, 0, 4, w_rel, nullptr, 0, 0);

    // 10+11+12. gated = u * (kernel[bg] @ v[bg] + linear)  (fused epi=3)
    // resid = u part of uv, batch stride NN_*UVW
    hgemm_kernel<0,0><<<dim3(12, 2, BB*GG), 256>>>(
        qkm, uv + EE, accb, gated, NN_, EE, NN_, NN_, UVW, EE,
        (long long)NN_*NN_, (long long)NN_*UVW, (long long)NN_*EE,
        1.f, 1, 3, nullptr, uv, UVW, (long long)NN_*UVW);

    // 13. out = gated @ W2 + b2 + shortcut   [32768,1536]x[1536,768]
    hgemm_kernel<0,0><<<dim3(6, 256, 1), 256>>>(
        gated, W2, outp, outp, TT, DD, EE, EE, DD, DD, 0, 0, 0,
        1.f, 0, 2, b2, inputs, DD, 0);
}

// round 13
// speedup vs baseline: 2.9610x; 1.4366x over previous
#include <cuda_runtime.h>
#include <cuda_bf16.h>
#include <cuda_fp16.h>
#include <math.h>
#include <stdint.h>

// Problem constants
#define BB 8
#define GG 16
#define NN_ 256
#define DD 768
#define EE 1536
#define SS 128
#define SEQ_ 512
#define TT (BB*GG*NN_)          // 32768 tokens
#define UVW (2*EE+SS)           // 3200

// ---------------- scratch (device globals; no allocations allowed) --------
__device__ __half g_xn[(long long)TT*DD];
__device__ __half g_uv[(long long)TT*UVW];
__device__ __half g_qq[(long long)TT*SS];
__device__ __half g_qkk[(long long)TT*SS];
__device__ __half g_lq[(long long)TT*SS];
__device__ __half g_lk[(long long)TT*SS];
__device__ __half g_kv[(long long)BB*SS*EE];
__device__ __half g_linv[(long long)TT*EE];
__device__ __half g_linkv[(long long)BB*GG*SS*EE];
__device__ __half g_linkv2[(long long)BB*GG*SS*EE];
__device__ float  g_accb[(long long)TT*EE];          // fp32: accumulated across GEMMs
__device__ __half g_qkm[(long long)BB*GG*NN_*NN_];
__device__ __half g_gated[(long long)TT*EE];
__device__ __half g_W1h[(long long)DD*UVW];
__device__ __half g_W2h[(long long)EE*DD];
__device__ float  g_invf[64];
__device__ int    g_mn[BB*GG];
__device__ int    g_mx[BB*GG];

// ---------------- asm helpers --------------------------------------------
__device__ __forceinline__ uint32_t s2u32(const void* p) {
    return (uint32_t)__cvta_generic_to_shared(p);
}
__device__ __forceinline__ void cp16(uint32_t dst, const void* src) {
    asm volatile("cp.async.cg.shared.global [%0], [%1], 16;\n" :: "r"(dst), "l"(src));
}
__device__ __forceinline__ void cp_commit() {
    asm volatile("cp.async.commit_group;\n");
}
template<int N>
__device__ __forceinline__ void cp_wait() {
    asm volatile("cp.async.wait_group %0;\n" :: "n"(N));
}
__device__ __forceinline__ void ldsm4(uint32_t& r0, uint32_t& r1, uint32_t& r2, uint32_t& r3,
                                      uint32_t addr) {
    asm volatile("ldmatrix.sync.aligned.m8n8.x4.shared.b16 {%0,%1,%2,%3}, [%4];\n"
                 : "=r"(r0), "=r"(r1), "=r"(r2), "=r"(r3) : "r"(addr));
}
__device__ __forceinline__ void ldsm4t(uint32_t& r0, uint32_t& r1, uint32_t& r2, uint32_t& r3,
                                       uint32_t addr) {
    asm volatile("ldmatrix.sync.aligned.m8n8.x4.trans.shared.b16 {%0,%1,%2,%3}, [%4];\n"
                 : "=r"(r0), "=r"(r1), "=r"(r2), "=r"(r3) : "r"(addr));
}
__device__ __forceinline__ void mma16(float& c0, float& c1, float& c2, float& c3,
                                      uint32_t a0, uint32_t a1, uint32_t a2, uint32_t a3,
                                      uint32_t b0, uint32_t b1)
{
    asm volatile(
        "mma.sync.aligned.m16n8k16.row.col.f32.f16.f16.f32 "
        "{%0,%1,%2,%3}, {%4,%5,%6,%7}, {%8,%9}, {%0,%1,%2,%3};"
        : "+f"(c0), "+f"(c1), "+f"(c2), "+f"(c3)
        : "r"(a0), "r"(a1), "r"(a2), "r"(a3), "r"(b0), "r"(b1));
}

// ---------------- fp16 tensor-core GEMM, cp.async double-buffered ---------
// 128x128 block tile, K-tile 32, 8 warps (2x4), warp tile 64x32.
// Global operands are fp16. Two smem tile layouts (16B chunk units):
//   RowTile: 128 rows x 5 chunks/row (32 data halves + pad)  [outer][k]
//   ColTile: 32 k-rows x 17 chunks/row (128 data halves + pad) [k][inner]
// TA=0: A RowTile + ldmatrix;        TA=1: A ColTile + ldmatrix.trans
// TB=0: B ColTile + ldmatrix.trans;  TB=1: B RowTile + ldmatrix
// epi: 0 none, 1 bias+silu, 2 bias+residual(f32), 3 gate ((acc+C)*resid_h),
//      4 toeplitz relu^2.  OHALF: 1 -> Cout is __half, 0 -> float.
// REQUIRES: M%128==0, N%128==0, K%32==0, lda/ldb%8==0 (all call sites satisfy).
template<int TA, int TB, int OHALF>
__global__ __launch_bounds__(256, 2)
void pgemm(const __half* __restrict__ A, const __half* __restrict__ B,
           const float* __restrict__ C, void* __restrict__ CoutV,
           int M, int N, int K, int lda, int ldb, int ldc,
           long long sA, long long sB, long long sC,
           float alpha, int accumulate, int epi,
           const float* __restrict__ bias,
           const void* __restrict__ residV, int ldr, long long sR)
{
    constexpr int ACH = TA ? (32 * 17) : (128 * 5);   // chunks per A stage
    constexpr int BCH = TB ? (128 * 5) : (32 * 17);   // chunks per B stage
    __shared__ __align__(16) uint4 sm[2 * (ACH + BCH)];

    int z = blockIdx.z;
    A += (long long)z * sA; B += (long long)z * sB;
    const float* Cacc = C + (long long)z * sC;
    int tid  = threadIdx.x;
    int lane = tid & 31;
    int warp = tid >> 5;
    int wm = (warp >> 2) * 64;
    int wn = (warp & 3) * 32;
    int bm = blockIdx.y * 128;
    int bn = blockIdx.x * 128;
    uint32_t smembase = s2u32(sm);

    float acc[4][4][4];
#pragma unroll
    for (int mf = 0; mf < 4; mf++)
#pragma unroll
        for (int nf = 0; nf < 4; nf++)
#pragma unroll
            for (int i = 0; i < 4; i++) acc[mf][nf][i] = 0.f;

    const int KT = K >> 5;

    auto copyTiles = [&](int kt, int st) {
        uint32_t sa = smembase + (uint32_t)st * (ACH + BCH) * 16;
        uint32_t sb = sa + ACH * 16;
        int k0 = kt << 5;
#pragma unroll
        for (int l = 0; l < 2; l++) {
            int idx = l * 256 + tid;
            if (TA == 0) { int m = idx >> 2, c = idx & 3;
                cp16(sa + (m * 5 + c) * 16, &A[(long long)(bm + m) * lda + k0 + c * 8]); }
            else         { int k = idx >> 4, c = idx & 15;
                cp16(sa + (k * 17 + c) * 16, &A[(long long)(k0 + k) * lda + bm + c * 8]); }
        }
#pragma unroll
        for (int l = 0; l < 2; l++) {
            int idx = l * 256 + tid;
            if (TB == 0) { int k = idx >> 4, c = idx & 15;
                cp16(sb + (k * 17 + c) * 16, &B[(long long)(k0 + k) * ldb + bn + c * 8]); }
            else         { int n = idx >> 2, c = idx & 3;
                cp16(sb + (n * 5 + c) * 16, &B[(long long)(bn + n) * ldb + k0 + c * 8]); }
        }
    };

    auto doMMA = [&](int st) {
        uint32_t sa = smembase + (uint32_t)st * (ACH + BCH) * 16;
        uint32_t sb = sa + ACH * 16;
#pragma unroll
        for (int ks = 0; ks < 2; ks++) {
            uint32_t af[4][4], bf[4][2];
#pragma unroll
            for (int mf = 0; mf < 4; mf++) {
                if (TA == 0) {
                    int row = wm + mf * 16 + (lane & 15);
                    uint32_t addr = sa + (uint32_t)(row * 5 + ks * 2 + (lane >> 4)) * 16;
                    ldsm4(af[mf][0], af[mf][1], af[mf][2], af[mf][3], addr);
                } else {
                    int kl = ((lane >> 4) << 3) + (lane & 7);
                    int mc = (wm + mf * 16) >> 3;
                    uint32_t addr = sa + (uint32_t)((ks * 16 + kl) * 17 + mc + ((lane >> 3) & 1)) * 16;
                    ldsm4t(af[mf][0], af[mf][1], af[mf][2], af[mf][3], addr);
                }
            }
#pragma unroll
            for (int nb = 0; nb < 2; nb++) {
                if (TB == 0) {
                    int kl = lane & 15;
                    int nc = (wn + nb * 16) >> 3;
                    uint32_t addr = sb + (uint32_t)((ks * 16 + kl) * 17 + nc + (lane >> 4)) * 16;
                    ldsm4t(bf[nb*2][0], bf[nb*2][1], bf[nb*2+1][0], bf[nb*2+1][1], addr);
                } else {
                    int nl = ((lane >> 4) << 3) + (lane & 7);
                    uint32_t addr = sb + (uint32_t)((wn + nb * 16 + nl) * 5 + ks * 2 + ((lane >> 3) & 1)) * 16;
                    ldsm4(bf[nb*2][0], bf[nb*2][1], bf[nb*2+1][0], bf[nb*2+1][1], addr);
                }
            }
#pragma unroll
            for (int mf = 0; mf < 4; mf++)
#pragma unroll
                for (int nf = 0; nf < 4; nf++)
                    mma16(acc[mf][nf][0], acc[mf][nf][1], acc[mf][nf][2], acc[mf][nf][3],
                          af[mf][0], af[mf][1], af[mf][2], af[mf][3],
                          bf[nf][0], bf[nf][1]);
        }
    };

    // prologue
    copyTiles(0, 0);
    cp_commit();

    for (int kt = 0; kt < KT; kt++) {
        int st = kt & 1;
        if (kt + 1 < KT) {
            copyTiles(kt + 1, st ^ 1);
            cp_commit();
            cp_wait<1>();
        } else {
            cp_wait<0>();
        }
        __syncthreads();
        doMMA(st);
        __syncthreads();
    }

    // ---- epilogue ----
    int g = lane >> 2, t = lane & 3;
    const float*  residF = (const float*)residV;
    const __half* residH = (const __half*)residV;
    if (residV) { residF += (long long)z * sR; residH += (long long)z * sR; }
    float*  outF = (float*) CoutV + (long long)z * sC;
    __half* outH = (__half*)CoutV + (long long)z * sC;
#pragma unroll
    for (int mf = 0; mf < 4; mf++) {
#pragma unroll
        for (int nf = 0; nf < 4; nf++) {
#pragma unroll
            for (int i = 0; i < 4; i++) {
                int row = bm + wm + mf * 16 + g + ((i >= 2) ? 8 : 0);
                int col = bn + wn + nf * 8 + 2 * t + (i & 1);
                float v = acc[mf][nf][i] * alpha;
                long long off = (long long)row * ldc + col;
                if (accumulate) v += Cacc[off];
                if (epi == 1) {
                    v += bias[col];
                    v = v / (1.f + expf(-v));          // silu
                } else if (epi == 2) {
                    v += bias[col] + residF[(long long)row * ldr + col];
                } else if (epi == 3) {
                    v *= __half2float(residH[(long long)row * ldr + col]);
                } else if (epi == 4) {
                    v += bias[SEQ_ - 1 + col - row];
                    v = fmaxf(v, 0.f);
                    v *= v;
                }
                if (OHALF) outH[off] = __float2half(v);
                else       outF[off] = v;
            }
        }
    }
}

// ---------------- fp32 -> fp16 convert ------------------------------------
__global__ void f2h_kernel(const float* __restrict__ src, __half* __restrict__ dst,
                           long long n)
{
    long long i = (long long)blockIdx.x * 256 + threadIdx.x;
    if (i < n) dst[i] = __float2half(src[i]);
}

// ---------------- layernorm (writes fp16) ---------------------------------
__global__ void ln_kernel(const float* __restrict__ x, const float* __restrict__ w,
                          const float* __restrict__ b, __half* __restrict__ y)
{
    int t = blockIdx.x;
    const float* row = x + (long long)t * DD;
    __half* outp = y + (long long)t * DD;
    __shared__ float red[8];
    __shared__ float s_mu, s_rstd;
    int tid = threadIdx.x;          // 256
    float s = 0.f;
    for (int i = tid; i < DD; i += 256) s += row[i];
#pragma unroll
    for (int o = 16; o > 0; o >>= 1) s += __shfl_xor_sync(0xffffffffu, s, o);
    if ((tid & 31) == 0) red[tid >> 5] = s;
    __syncthreads();
    if (tid == 0) {
        float tot = 0.f;
        for (int i = 0; i < 8; i++) tot += red[i];
        s_mu = tot / (float)DD;
    }
    __syncthreads();
    float mu = s_mu;
    float vs = 0.f;
    for (int i = tid; i < DD; i += 256) { float d = row[i] - mu; vs += d * d; }
#pragma unroll
    for (int o = 16; o > 0; o >>= 1) vs += __shfl_xor_sync(0xffffffffu, vs, o);
    if ((tid & 31) == 0) red[tid >> 5] = vs;
    __syncthreads();
    if (tid == 0) {
        float tot = 0.f;
        for (int i = 0; i < 8; i++) tot += red[i];
        s_rstd = rsqrtf(tot / (float)DD + 1e-5f);
    }
    __syncthreads();
    float rstd = s_rstd;
    for (int i = tid; i < DD; i += 256)
        outp[i] = __float2half((row[i] - mu) * rstd * w[i] + b[i]);
}

// ---------------- inv_freq (double precision, correctly rounded fp32) -----
__global__ void invf_kernel(float* g)
{
    int j = threadIdx.x;
    if (j < 64) g[j] = (float)exp(log(10000.0) * ((double)j / 64.0));
}

// ---------------- affine (gamma/beta) + RoPE -> 4 fp16 components ---------
__global__ void rope_kernel(const __half* __restrict__ uv, const float* __restrict__ gamma,
                            const float* __restrict__ beta, const float* __restrict__ invf,
                            __half* __restrict__ qq, __half* __restrict__ qk,
                            __half* __restrict__ lq, __half* __restrict__ lk)
{
    int t = blockIdx.x;             // token
    int j = threadIdx.x;            // 0..63
    int g = (t >> 8) & (GG - 1);
    int n = t & (NN_ - 1);
    float p = (float)((g << 8) + n);
    float arg = p * invf[j];
    float sn, cs;
    sincosf(arg, &sn, &cs);
    const __half* zp = uv + (long long)t * UVW + 2 * EE;
    float z1 = __half2float(zp[j]), z2 = __half2float(zp[j + 64]);
    __half* outs[4] = {qq, qk, lq, lk};
#pragma unroll
    for (int i = 0; i < 4; i++) {
        float a1 = z1 * gamma[i * SS + j]      + beta[i * SS + j];
        float a2 = z2 * gamma[i * SS + 64 + j] + beta[i * SS + 64 + j];
        __half* o = outs[i] + (long long)t * SS;
        o[j]      = __float2half(a1 * cs - a2 * sn);
        o[j + 64] = __float2half(a2 * cs + a1 * sn);
    }
}

// ---------------- segment min/max per (b,g) -------------------------------
__global__ void minmax_kernel(const int* __restrict__ seg, int* __restrict__ mn,
                              int* __restrict__ mx)
{
    int bg = blockIdx.x;
    int tid = threadIdx.x;          // 256
    int v = seg[(long long)bg * NN_ + tid];
    int a = v, b = v;
#pragma unroll
    for (int o = 16; o > 0; o >>= 1) {
        a = min(a, __shfl_xor_sync(0xffffffffu, a, o));
        b = max(b, __shfl_xor_sync(0xffffffffu, b, o));
    }
    __shared__ int smn[8], smx[8];
    if ((tid & 31) == 0) { smn[tid >> 5] = a; smx[tid >> 5] = b; }
    __syncthreads();
    if (tid == 0) {
        int aa = smn[0], bb = smx[0];
        for (int i = 1; i < 8; i++) { aa = min(aa, smn[i]); bb = max(bb, smx[i]); }
        mn[bg] = aa; mx[bg] = bb;
    }
}

// ---------------- group mixing: read-once, accumulate 16 outputs ----------
__global__ void mix_kernel(const __half* __restrict__ lin_kv, const int* __restrict__ mn,
                           const int* __restrict__ mx, __half* __restrict__ outp)
{
    const long long SE = (long long)SS * EE;   // 196608
    int b = blockIdx.y;
    int tid = threadIdx.x;
    __shared__ float w[16][16];
    {
        int g = tid >> 4, h = tid & 15;
        if (tid < 256) {
            int mng = mn[b * 16 + g], mxg = mx[b * 16 + g];
            int ov = (mng <= mx[b * 16 + h] && mxg >= mn[b * 16 + h]) ? 1 : 0;
            w[g][h] = (float)ov;
        }
    }
    __syncthreads();
    if (tid < 16) {
        float s = 0.f;
        for (int h = 0; h < 16; h++) s += w[tid][h];
        float inv = 1.f / s;
        for (int h = 0; h < 16; h++) w[tid][h] *= inv;
    }
    __syncthreads();

    long long idx = (long long)blockIdx.x * 256 + tid;     // 0..SE
    const __half* src = lin_kv + (long long)b * 16 * SE + idx;
    float o[16];
#pragma unroll
    for (int g = 0; g < 16; g++) o[g] = 0.f;
#pragma unroll
    for (int h = 0; h < 16; h++) {
        float v = __half2float(src[(long long)h * SE]);
#pragma unroll
        for (int g = 0; g < 16; g++) o[g] = fmaf(w[g][h], v, o[g]);
    }
    __half* dst = outp + (long long)b * 16 * SE + idx;
#pragma unroll
    for (int g = 0; g < 16; g++) dst[(long long)g * SE] = __float2half(o[g]);
}

// ---------------- launch ---------------------------------------------------
extern "C" void kernel_launch(void* const* d_in, const int* in_sizes, int n_in,
                              void* d_out, int out_size)
{
    const float* inputs = (const float*)d_in[0];
    const int*   seg    = (const int*)  d_in[1];
    const float* ln_w   = (const float*)d_in[2];
    const float* ln_b   = (const float*)d_in[3];
    const float* W1     = (const float*)d_in[4];
    const float* b1     = (const float*)d_in[5];
    const float* gamma  = (const float*)d_in[6];
    const float* beta   = (const float*)d_in[7];
    const float* W2     = (const float*)d_in[8];
    const float* b2     = (const float*)d_in[9];
    const float* w_rel  = (const float*)d_in[10];
    float* outp = (float*)d_out;

    __half *xn, *uv, *qq, *qkk, *lq, *lk, *kv, *linv, *linkv, *linkv2, *qkm, *gated, *W1h, *W2h;
    float *accb, *invf;
    int *mn, *mx;
    cudaGetSymbolAddress((void**)&xn,    g_xn);
    cudaGetSymbolAddress((void**)&uv,    g_uv);
    cudaGetSymbolAddress((void**)&qq,    g_qq);
    cudaGetSymbolAddress((void**)&qkk,   g_qkk);
    cudaGetSymbolAddress((void**)&lq,    g_lq);
    cudaGetSymbolAddress((void**)&lk,    g_lk);
    cudaGetSymbolAddress((void**)&kv,    g_kv);
    cudaGetSymbolAddress((void**)&linv,  g_linv);
    cudaGetSymbolAddress((void**)&linkv, g_linkv);
    cudaGetSymbolAddress((void**)&linkv2,g_linkv2);
    cudaGetSymbolAddress((void**)&accb,  g_accb);
    cudaGetSymbolAddress((void**)&qkm,   g_qkm);
    cudaGetSymbolAddress((void**)&gated, g_gated);
    cudaGetSymbolAddress((void**)&W1h,   g_W1h);
    cudaGetSymbolAddress((void**)&W2h,   g_W2h);
    cudaGetSymbolAddress((void**)&invf,  g_invf);
    cudaGetSymbolAddress((void**)&mn,    g_mn);
    cudaGetSymbolAddress((void**)&mx,    g_mx);

    // 0. weight conversion (cheap) + LN + inv_freq
    f2h_kernel<<<((long long)DD*UVW + 255)/256, 256>>>(W1, W1h, (long long)DD*UVW);
    f2h_kernel<<<((long long)EE*DD  + 255)/256, 256>>>(W2, W2h, (long long)EE*DD);
    ln_kernel<<<TT, 256>>>(inputs, ln_w, ln_b, xn);
    invf_kernel<<<1, 64>>>(invf);

    // 2. uv = silu(xn @ W1 + b1)   [32768,768]x[768,3200] -> fp16
    pgemm<0,0,1><<<dim3(25, 256, 1), 256>>>(
        xn, W1h, nullptr, uv, TT, UVW, DD, DD, UVW, UVW, 0, 0, 0,
        1.f, 0, 1, b1, nullptr, 0, 0);

    // 3. RoPE components (fp16 in/out)
    rope_kernel<<<TT, 64>>>(uv, gamma, beta, invf, qq, qkk, lq, lk);

    // 4. kv[b] = lin_k[b]^T @ v[b]   per b: [4096,128]^T x [4096,1536]
    pgemm<1,0,1><<<dim3(12, 1, BB), 256>>>(
        lk, uv + EE, nullptr, kv, SS, EE, GG*NN_, SS, UVW, EE,
        (long long)GG*NN_*SS, (long long)GG*NN_*UVW, (long long)SS*EE,
        1.f, 0, 0, nullptr, nullptr, 0, 0);

    // 5. lin_v[b] = lin_q[b] @ kv[b]   per b: [4096,128] x [128,1536]
    pgemm<0,0,1><<<dim3(12, 32, BB), 256>>>(
        lq, kv, nullptr, linv, GG*NN_, EE, SS, SS, EE, EE,
        (long long)GG*NN_*SS, (long long)SS*EE, (long long)GG*NN_*EE,
        1.f, 0, 0, nullptr, nullptr, 0, 0);

    // 6. lin_kv[bg] = lin_k[bg]^T @ lin_v[bg] / n   per bg: [256,128]^T x [256,1536]
    pgemm<1,0,1><<<dim3(12, 1, BB*GG), 256>>>(
        lk, linv, nullptr, linkv, SS, EE, NN_, SS, EE, EE,
        (long long)NN_*SS, (long long)NN_*EE, (long long)SS*EE,
        1.f / (float)NN_, 0, 0, nullptr, nullptr, 0, 0);

    // 7. segment mask mixing
    minmax_kernel<<<BB*GG, 256>>>(seg, mn, mx);
    mix_kernel<<<dim3((SS*EE)/256, BB), 256>>>(linkv, mn, mx, linkv2);

    // 8. linear[bg] = lin_q[bg] @ lin_kv2[bg] -> accb (fp32)
    pgemm<0,0,0><<<dim3(12, 2, BB*GG), 256>>>(
        lq, linkv2, nullptr, accb, NN_, EE, SS, SS, EE, EE,
        (long long)NN_*SS, (long long)SS*EE, (long long)NN_*EE,
        1.f, 0, 0, nullptr, nullptr, 0, 0);

    // 9. qk[bg] = relu(quad_q@quad_k^T/n + toeplitz)^2 -> fp16 (epi=4)
    pgemm<0,1,1><<<dim3(2, 2, BB*GG), 256>>>(
        qq, qkk, nullptr, qkm, NN_, NN_, SS, SS, SS, NN_,
        (long long)NN_*SS, (long long)NN_*SS, (long long)NN_*NN_,
        1.f / (float)NN_, 0, 4, w_rel, nullptr, 0, 0);

    // 10+11+12. gated = u * (kernel[bg] @ v[bg] + linear)  (epi=3, resid=u fp16)
    pgemm<0,0,1><<<dim3(12, 2, BB*GG), 256>>>(
        qkm, uv + EE, accb, gated, NN_, EE, NN_, NN_, UVW, EE,
        (long long)NN_*NN_, (long long)NN_*UVW, (long long)NN_*EE,
        1.f, 1, 3, nullptr, uv, UVW, (long long)NN_*UVW);

    // 13. out = gated @ W2 + b2 + shortcut   [32768,1536]x[1536,768] -> fp32
    pgemm<0,0,0><<<dim3(6, 256, 1), 256>>>(
        gated, W2h, nullptr, outp, TT, DD, EE, EE, DD, DD, 0, 0, 0,
        1.f, 0, 2, b2, inputs, DD, 0);
}

// round 14
// speedup vs baseline: 3.1319x; 1.0577x over previous
#include <cuda_runtime.h>
#include <cuda_bf16.h>
#include <cuda_fp16.h>
#include <math.h>
#include <stdint.h>

// Problem constants
#define BB 8
#define GG 16
#define NN_ 256
#define DD 768
#define EE 1536
#define SS 128
#define SEQ_ 512
#define TT (BB*GG*NN_)          // 32768 tokens
#define UVW (2*EE+SS)           // 3200

// ---------------- scratch (device globals; no allocations allowed) --------
__device__ __half g_xn[(long long)TT*DD];
__device__ __half g_uv[(long long)TT*UVW];
__device__ __half g_qq[(long long)TT*SS];
__device__ __half g_qkk[(long long)TT*SS];
__device__ __half g_lq[(long long)TT*SS];
__device__ __half g_lk[(long long)TT*SS];
__device__ __half g_kv[(long long)BB*SS*EE];
__device__ __half g_linv[(long long)TT*EE];
__device__ __half g_linkv[(long long)BB*GG*SS*EE];
__device__ __half g_linkv2[(long long)BB*GG*SS*EE];
__device__ __half g_qkm[(long long)BB*GG*NN_*NN_];
__device__ __half g_gated[(long long)TT*EE];
__device__ __half g_W1h[(long long)DD*UVW];
__device__ __half g_W2h[(long long)EE*DD];
__device__ float  g_invf[64];
__device__ int    g_mn[BB*GG];
__device__ int    g_mx[BB*GG];

// ---------------- asm helpers --------------------------------------------
__device__ __forceinline__ uint32_t s2u32(const void* p) {
    return (uint32_t)__cvta_generic_to_shared(p);
}
__device__ __forceinline__ void cp16(uint32_t dst, const void* src) {
    asm volatile("cp.async.cg.shared.global [%0], [%1], 16;\n" :: "r"(dst), "l"(src));
}
__device__ __forceinline__ void cp_commit() {
    asm volatile("cp.async.commit_group;\n");
}
template<int N>
__device__ __forceinline__ void cp_wait() {
    asm volatile("cp.async.wait_group %0;\n" :: "n"(N));
}
__device__ __forceinline__ void ldsm4(uint32_t& r0, uint32_t& r1, uint32_t& r2, uint32_t& r3,
                                      uint32_t addr) {
    asm volatile("ldmatrix.sync.aligned.m8n8.x4.shared.b16 {%0,%1,%2,%3}, [%4];\n"
                 : "=r"(r0), "=r"(r1), "=r"(r2), "=r"(r3) : "r"(addr));
}
__device__ __forceinline__ void ldsm4t(uint32_t& r0, uint32_t& r1, uint32_t& r2, uint32_t& r3,
                                       uint32_t addr) {
    asm volatile("ldmatrix.sync.aligned.m8n8.x4.trans.shared.b16 {%0,%1,%2,%3}, [%4];\n"
                 : "=r"(r0), "=r"(r1), "=r"(r2), "=r"(r3) : "r"(addr));
}
__device__ __forceinline__ void mma16(float& c0, float& c1, float& c2, float& c3,
                                      uint32_t a0, uint32_t a1, uint32_t a2, uint32_t a3,
                                      uint32_t b0, uint32_t b1)
{
    asm volatile(
        "mma.sync.aligned.m16n8k16.row.col.f32.f16.f16.f32 "
        "{%0,%1,%2,%3}, {%4,%5,%6,%7}, {%8,%9}, {%0,%1,%2,%3};"
        : "+f"(c0), "+f"(c1), "+f"(c2), "+f"(c3)
        : "r"(a0), "r"(a1), "r"(a2), "r"(a3), "r"(b0), "r"(b1));
}

// Smem chunk counts (16B units) per stage
#define ROWCH (128*5)     // RowTile: 128 rows x 5 chunks
#define COLCH (32*17)     // ColTile: 32 k-rows x 17 chunks

// ---------------- fp16 tensor-core GEMM, 3-stage cp.async pipeline --------
// 128x128 block tile, K-tile 32, 8 warps (2x4), warp tile 64x32, dyn smem.
// TA=0: A RowTile + ldmatrix;        TA=1: A ColTile + ldmatrix.trans
// TB=0: B ColTile + ldmatrix.trans;  TB=1: B RowTile + ldmatrix
// epi: 0 none, 1 bias+silu, 2 bias+residual(f32), 4 toeplitz relu^2.
// OHALF: 1 -> Cout __half, 0 -> float.
template<int TA, int TB, int OHALF>
__global__ __launch_bounds__(256, 2)
void pgemm(const __half* __restrict__ A, const __half* __restrict__ B,
           void* __restrict__ CoutV,
           int M, int N, int K, int lda, int ldb, int ldc,
           long long sA, long long sB, long long sC,
           float alpha, int epi,
           const float* __restrict__ bias,
           const float* __restrict__ residF, int ldr)
{
    constexpr int ACH = TA ? COLCH : ROWCH;
    constexpr int BCH = TB ? ROWCH : COLCH;
    constexpr int STG = ACH + BCH;
    extern __shared__ __align__(16) uint4 smd[];

    int z = blockIdx.z;
    A += (long long)z * sA; B += (long long)z * sB;
    int tid  = threadIdx.x;
    int lane = tid & 31;
    int warp = tid >> 5;
    int wm = (warp >> 2) * 64;
    int wn = (warp & 3) * 32;
    int bm = blockIdx.y * 128;
    int bn = blockIdx.x * 128;
    uint32_t smembase = s2u32(smd);

    float acc[4][4][4];
#pragma unroll
    for (int mf = 0; mf < 4; mf++)
#pragma unroll
        for (int nf = 0; nf < 4; nf++)
#pragma unroll
            for (int i = 0; i < 4; i++) acc[mf][nf][i] = 0.f;

    const int KT = K >> 5;

    auto copyTiles = [&](int kt, int st) {
        uint32_t sa = smembase + (uint32_t)st * STG * 16;
        uint32_t sb = sa + ACH * 16;
        int k0 = kt << 5;
#pragma unroll
        for (int l = 0; l < 2; l++) {
            int idx = l * 256 + tid;
            if (TA == 0) { int m = idx >> 2, c = idx & 3;
                cp16(sa + (m * 5 + c) * 16, &A[(long long)(bm + m) * lda + k0 + c * 8]); }
            else         { int k = idx >> 4, c = idx & 15;
                cp16(sa + (k * 17 + c) * 16, &A[(long long)(k0 + k) * lda + bm + c * 8]); }
        }
#pragma unroll
        for (int l = 0; l < 2; l++) {
            int idx = l * 256 + tid;
            if (TB == 0) { int k = idx >> 4, c = idx & 15;
                cp16(sb + (k * 17 + c) * 16, &B[(long long)(k0 + k) * ldb + bn + c * 8]); }
            else         { int n = idx >> 2, c = idx & 3;
                cp16(sb + (n * 5 + c) * 16, &B[(long long)(bn + n) * ldb + k0 + c * 8]); }
        }
    };

    auto doMMA = [&](int st) {
        uint32_t sa = smembase + (uint32_t)st * STG * 16;
        uint32_t sb = sa + ACH * 16;
#pragma unroll
        for (int ks = 0; ks < 2; ks++) {
            uint32_t af[4][4], bf[4][2];
#pragma unroll
            for (int mf = 0; mf < 4; mf++) {
                if (TA == 0) {
                    int row = wm + mf * 16 + (lane & 15);
                    uint32_t addr = sa + (uint32_t)(row * 5 + ks * 2 + (lane >> 4)) * 16;
                    ldsm4(af[mf][0], af[mf][1], af[mf][2], af[mf][3], addr);
                } else {
                    int kl = ((lane >> 4) << 3) + (lane & 7);
                    int mc = (wm + mf * 16) >> 3;
                    uint32_t addr = sa + (uint32_t)((ks * 16 + kl) * 17 + mc + ((lane >> 3) & 1)) * 16;
                    ldsm4t(af[mf][0], af[mf][1], af[mf][2], af[mf][3], addr);
                }
            }
#pragma unroll
            for (int nb = 0; nb < 2; nb++) {
                if (TB == 0) {
                    int kl = lane & 15;
                    int nc = (wn + nb * 16) >> 3;
                    uint32_t addr = sb + (uint32_t)((ks * 16 + kl) * 17 + nc + (lane >> 4)) * 16;
                    ldsm4t(bf[nb*2][0], bf[nb*2][1], bf[nb*2+1][0], bf[nb*2+1][1], addr);
                } else {
                    int nl = ((lane >> 4) << 3) + (lane & 7);
                    uint32_t addr = sb + (uint32_t)((wn + nb * 16 + nl) * 5 + ks * 2 + ((lane >> 3) & 1)) * 16;
                    ldsm4(bf[nb*2][0], bf[nb*2][1], bf[nb*2+1][0], bf[nb*2+1][1], addr);
                }
            }
#pragma unroll
            for (int mf = 0; mf < 4; mf++)
#pragma unroll
                for (int nf = 0; nf < 4; nf++)
                    mma16(acc[mf][nf][0], acc[mf][nf][1], acc[mf][nf][2], acc[mf][nf][3],
                          af[mf][0], af[mf][1], af[mf][2], af[mf][3],
                          bf[nf][0], bf[nf][1]);
        }
    };

    // 3-stage pipeline: one __syncthreads per iteration
    copyTiles(0, 0); cp_commit();
    if (KT > 1) { copyTiles(1, 1); cp_commit(); }

    for (int kt = 0; kt < KT; kt++) {
        int st = kt % 3;
        if (kt == KT - 1) cp_wait<0>(); else cp_wait<1>();
        __syncthreads();
        if (kt + 2 < KT) { copyTiles(kt + 2, (kt + 2) % 3); cp_commit(); }
        doMMA(st);
    }

    // ---- epilogue ----
    int g = lane >> 2, t = lane & 3;
    float*  outF = (float*) CoutV + (long long)z * sC;
    __half* outH = (__half*)CoutV + (long long)z * sC;
#pragma unroll
    for (int mf = 0; mf < 4; mf++) {
#pragma unroll
        for (int nf = 0; nf < 4; nf++) {
#pragma unroll
            for (int i = 0; i < 4; i++) {
                int row = bm + wm + mf * 16 + g + ((i >= 2) ? 8 : 0);
                int col = bn + wn + nf * 8 + 2 * t + (i & 1);
                float v = acc[mf][nf][i] * alpha;
                long long off = (long long)row * ldc + col;
                if (epi == 1) {
                    v += bias[col];
                    v = v / (1.f + expf(-v));          // silu
                } else if (epi == 2) {
                    v += bias[col] + residF[(long long)row * ldr + col];
                } else if (epi == 4) {
                    v += bias[SEQ_ - 1 + col - row];
                    v = fmaxf(v, 0.f);
                    v *= v;
                }
                if (OHALF) outH[off] = __float2half(v);
                else       outF[off] = v;
            }
        }
    }
}

// ---------------- dual GEMM: gated = u * (lq@linkv2 + qkm@v) --------------
// Per bg (z): phase1 A=lq[256,128] B=linkv2[128,1536]; phase2 A=qkm[256,256]
// B=v[256,1536]. Both TA=0,TB=0. One register accumulator, gate epilogue.
__global__ __launch_bounds__(256, 2)
void dualgemm(const __half* __restrict__ lq, const __half* __restrict__ linkv2,
              const __half* __restrict__ qkm, const __half* __restrict__ uvb,
              __half* __restrict__ outp)
{
    constexpr int ACH = ROWCH, BCH = COLCH, STG = ACH + BCH;
    extern __shared__ __align__(16) uint4 smd[];

    int z = blockIdx.z;
    const __half* A1 = lq     + (long long)z * NN_ * SS;
    const __half* B1 = linkv2 + (long long)z * SS * EE;
    const __half* A2 = qkm    + (long long)z * NN_ * NN_;
    const __half* B2 = uvb + EE + (long long)z * NN_ * UVW;   // v slice
    const __half* U  = uvb      + (long long)z * NN_ * UVW;   // u slice
    __half* out = outp + (long long)z * NN_ * EE;

    int tid  = threadIdx.x;
    int lane = tid & 31;
    int warp = tid >> 5;
    int wm = (warp >> 2) * 64;
    int wn = (warp & 3) * 32;
    int bm = blockIdx.y * 128;
    int bn = blockIdx.x * 128;
    uint32_t smembase = s2u32(smd);

    float acc[4][4][4];
#pragma unroll
    for (int mf = 0; mf < 4; mf++)
#pragma unroll
        for (int nf = 0; nf < 4; nf++)
#pragma unroll
            for (int i = 0; i < 4; i++) acc[mf][nf][i] = 0.f;

    auto runPhase = [&](const __half* A, int lda, const __half* B, int ldb, int KT) {
        auto copyTiles = [&](int kt, int st) {
            uint32_t sa = smembase + (uint32_t)st * STG * 16;
            uint32_t sb = sa + ACH * 16;
            int k0 = kt << 5;
#pragma unroll
            for (int l = 0; l < 2; l++) {
                int idx = l * 256 + tid;
                int m = idx >> 2, c = idx & 3;
                cp16(sa + (m * 5 + c) * 16, &A[(long long)(bm + m) * lda + k0 + c * 8]);
            }
#pragma unroll
            for (int l = 0; l < 2; l++) {
                int idx = l * 256 + tid;
                int k = idx >> 4, c = idx & 15;
                cp16(sb + (k * 17 + c) * 16, &B[(long long)(k0 + k) * ldb + bn + c * 8]);
            }
        };
        auto doMMA = [&](int st) {
            uint32_t sa = smembase + (uint32_t)st * STG * 16;
            uint32_t sb = sa + ACH * 16;
#pragma unroll
            for (int ks = 0; ks < 2; ks++) {
                uint32_t af[4][4], bf[4][2];
#pragma unroll
                for (int mf = 0; mf < 4; mf++) {
                    int row = wm + mf * 16 + (lane & 15);
                    uint32_t addr = sa + (uint32_t)(row * 5 + ks * 2 + (lane >> 4)) * 16;
                    ldsm4(af[mf][0], af[mf][1], af[mf][2], af[mf][3], addr);
                }
#pragma unroll
                for (int nb = 0; nb < 2; nb++) {
                    int kl = lane & 15;
                    int nc = (wn + nb * 16) >> 3;
                    uint32_t addr = sb + (uint32_t)((ks * 16 + kl) * 17 + nc + (lane >> 4)) * 16;
                    ldsm4t(bf[nb*2][0], bf[nb*2][1], bf[nb*2+1][0], bf[nb*2+1][1], addr);
                }
#pragma unroll
                for (int mf = 0; mf < 4; mf++)
#pragma unroll
                    for (int nf = 0; nf < 4; nf++)
                        mma16(acc[mf][nf][0], acc[mf][nf][1], acc[mf][nf][2], acc[mf][nf][3],
                              af[mf][0], af[mf][1], af[mf][2], af[mf][3],
                              bf[nf][0], bf[nf][1]);
            }
        };

        copyTiles(0, 0); cp_commit();
        if (KT > 1) { copyTiles(1, 1); cp_commit(); }
        for (int kt = 0; kt < KT; kt++) {
            int st = kt % 3;
            if (kt == KT - 1) cp_wait<0>(); else cp_wait<1>();
            __syncthreads();
            if (kt + 2 < KT) { copyTiles(kt + 2, (kt + 2) % 3); cp_commit(); }
            doMMA(st);
        }
        __syncthreads();   // all warps done reading before next phase reuses buffers
    };

    runPhase(A1, SS, B1, EE, SS >> 5);    // K=128
    runPhase(A2, NN_, B2, UVW, NN_ >> 5); // K=256

    // gate epilogue
    int g = lane >> 2, t = lane & 3;
#pragma unroll
    for (int mf = 0; mf < 4; mf++) {
#pragma unroll
        for (int nf = 0; nf < 4; nf++) {
#pragma unroll
            for (int i = 0; i < 4; i++) {
                int row = bm + wm + mf * 16 + g + ((i >= 2) ? 8 : 0);
                int col = bn + wn + nf * 8 + 2 * t + (i & 1);
                float v = acc[mf][nf][i] *
                          __half2float(U[(long long)row * UVW + col]);
                out[(long long)row * EE + col] = __float2half(v);
            }
        }
    }
}

// ---------------- fp32 -> fp16 convert ------------------------------------
__global__ void f2h_kernel(const float* __restrict__ src, __half* __restrict__ dst,
                           long long n)
{
    long long i = (long long)blockIdx.x * 256 + threadIdx.x;
    if (i < n) dst[i] = __float2half(src[i]);
}

// ---------------- layernorm (writes fp16) ---------------------------------
__global__ void ln_kernel(const float* __restrict__ x, const float* __restrict__ w,
                          const float* __restrict__ b, __half* __restrict__ y)
{
    int t = blockIdx.x;
    const float* row = x + (long long)t * DD;
    __half* outp = y + (long long)t * DD;
    __shared__ float red[8];
    __shared__ float s_mu, s_rstd;
    int tid = threadIdx.x;          // 256
    float s = 0.f;
    for (int i = tid; i < DD; i += 256) s += row[i];
#pragma unroll
    for (int o = 16; o > 0; o >>= 1) s += __shfl_xor_sync(0xffffffffu, s, o);
    if ((tid & 31) == 0) red[tid >> 5] = s;
    __syncthreads();
    if (tid == 0) {
        float tot = 0.f;
        for (int i = 0; i < 8; i++) tot += red[i];
        s_mu = tot / (float)DD;
    }
    __syncthreads();
    float mu = s_mu;
    float vs = 0.f;
    for (int i = tid; i < DD; i += 256) { float d = row[i] - mu; vs += d * d; }
#pragma unroll
    for (int o = 16; o > 0; o >>= 1) vs += __shfl_xor_sync(0xffffffffu, vs, o);
    if ((tid & 31) == 0) red[tid >> 5] = vs;
    __syncthreads();
    if (tid == 0) {
        float tot = 0.f;
        for (int i = 0; i < 8; i++) tot += red[i];
        s_rstd = rsqrtf(tot / (float)DD + 1e-5f);
    }
    __syncthreads();
    float rstd = s_rstd;
    for (int i = tid; i < DD; i += 256)
        outp[i] = __float2half((row[i] - mu) * rstd * w[i] + b[i]);
}

// ---------------- inv_freq (double precision, correctly rounded fp32) -----
__global__ void invf_kernel(float* g)
{
    int j = threadIdx.x;
    if (j < 64) g[j] = (float)exp(log(10000.0) * ((double)j / 64.0));
}

// ---------------- affine (gamma/beta) + RoPE -> 4 fp16 components ---------
__global__ void rope_kernel(const __half* __restrict__ uv, const float* __restrict__ gamma,
                            const float* __restrict__ beta, const float* __restrict__ invf,
                            __half* __restrict__ qq, __half* __restrict__ qk,
                            __half* __restrict__ lq, __half* __restrict__ lk)
{
    int t = blockIdx.x;             // token
    int j = threadIdx.x;            // 0..63
    int g = (t >> 8) & (GG - 1);
    int n = t & (NN_ - 1);
    float p = (float)((g << 8) + n);
    float arg = p * invf[j];
    float sn, cs;
    sincosf(arg, &sn, &cs);
    const __half* zp = uv + (long long)t * UVW + 2 * EE;
    float z1 = __half2float(zp[j]), z2 = __half2float(zp[j + 64]);
    __half* outs[4] = {qq, qk, lq, lk};
#pragma unroll
    for (int i = 0; i < 4; i++) {
        float a1 = z1 * gamma[i * SS + j]      + beta[i * SS + j];
        float a2 = z2 * gamma[i * SS + 64 + j] + beta[i * SS + 64 + j];
        __half* o = outs[i] + (long long)t * SS;
        o[j]      = __float2half(a1 * cs - a2 * sn);
        o[j + 64] = __float2half(a2 * cs + a1 * sn);
    }
}

// ---------------- segment min/max per (b,g) -------------------------------
__global__ void minmax_kernel(const int* __restrict__ seg, int* __restrict__ mn,
                              int* __restrict__ mx)
{
    int bg = blockIdx.x;
    int tid = threadIdx.x;          // 256
    int v = seg[(long long)bg * NN_ + tid];
    int a = v, b = v;
#pragma unroll
    for (int o = 16; o > 0; o >>= 1) {
        a = min(a, __shfl_xor_sync(0xffffffffu, a, o));
        b = max(b, __shfl_xor_sync(0xffffffffu, b, o));
    }
    __shared__ int smn[8], smx[8];
    if ((tid & 31) == 0) { smn[tid >> 5] = a; smx[tid >> 5] = b; }
    __syncthreads();
    if (tid == 0) {
        int aa = smn[0], bb = smx[0];
        for (int i = 1; i < 8; i++) { aa = min(aa, smn[i]); bb = max(bb, smx[i]); }
        mn[bg] = aa; mx[bg] = bb;
    }
}

// ---------------- group mixing: read-once, accumulate 16 outputs ----------
__global__ void mix_kernel(const __half* __restrict__ lin_kv, const int* __restrict__ mn,
                           const int* __restrict__ mx, __half* __restrict__ outp)
{
    const long long SE = (long long)SS * EE;   // 196608
    int b = blockIdx.y;
    int tid = threadIdx.x;
    __shared__ float w[16][16];
    {
        int g = tid >> 4, h = tid & 15;
        if (tid < 256) {
            int mng = mn[b * 16 + g], mxg = mx[b * 16 + g];
            int ov = (mng <= mx[b * 16 + h] && mxg >= mn[b * 16 + h]) ? 1 : 0;
            w[g][h] = (float)ov;
        }
    }
    __syncthreads();
    if (tid < 16) {
        float s = 0.f;
        for (int h = 0; h < 16; h++) s += w[tid][h];
        float inv = 1.f / s;
        for (int h = 0; h < 16; h++) w[tid][h] *= inv;
    }
    __syncthreads();

    long long idx = (long long)blockIdx.x * 256 + tid;     // 0..SE
    const __half* src = lin_kv + (long long)b * 16 * SE + idx;
    float o[16];
#pragma unroll
    for (int g = 0; g < 16; g++) o[g] = 0.f;
#pragma unroll
    for (int h = 0; h < 16; h++) {
        float v = __half2float(src[(long long)h * SE]);
#pragma unroll
        for (int g = 0; g < 16; g++) o[g] = fmaf(w[g][h], v, o[g]);
    }
    __half* dst = outp + (long long)b * 16 * SE + idx;
#pragma unroll
    for (int g = 0; g < 16; g++) dst[(long long)g * SE] = __float2half(o[g]);
}

// ---------------- launch ---------------------------------------------------
extern "C" void kernel_launch(void* const* d_in, const int* in_sizes, int n_in,
                              void* d_out, int out_size)
{
    const float* inputs = (const float*)d_in[0];
    const int*   seg    = (const int*)  d_in[1];
    const float* ln_w   = (const float*)d_in[2];
    const float* ln_b   = (const float*)d_in[3];
    const float* W1     = (const float*)d_in[4];
    const float* b1     = (const float*)d_in[5];
    const float* gamma  = (const float*)d_in[6];
    const float* beta   = (const float*)d_in[7];
    const float* W2     = (const float*)d_in[8];
    const float* b2     = (const float*)d_in[9];
    const float* w_rel  = (const float*)d_in[10];
    float* outp = (float*)d_out;

    __half *xn, *uv, *qq, *qkk, *lq, *lk, *kv, *linv, *linkv, *linkv2, *qkm, *gated, *W1h, *W2h;
    float *invf;
    int *mn, *mx;
    cudaGetSymbolAddress((void**)&xn,    g_xn);
    cudaGetSymbolAddress((void**)&uv,    g_uv);
    cudaGetSymbolAddress((void**)&qq,    g_qq);
    cudaGetSymbolAddress((void**)&qkk,   g_qkk);
    cudaGetSymbolAddress((void**)&lq,    g_lq);
    cudaGetSymbolAddress((void**)&lk,    g_lk);
    cudaGetSymbolAddress((void**)&kv,    g_kv);
    cudaGetSymbolAddress((void**)&linv,  g_linv);
    cudaGetSymbolAddress((void**)&linkv, g_linkv);
    cudaGetSymbolAddress((void**)&linkv2,g_linkv2);
    cudaGetSymbolAddress((void**)&qkm,   g_qkm);
    cudaGetSymbolAddress((void**)&gated, g_gated);
    cudaGetSymbolAddress((void**)&W1h,   g_W1h);
    cudaGetSymbolAddress((void**)&W2h,   g_W2h);
    cudaGetSymbolAddress((void**)&invf,  g_invf);
    cudaGetSymbolAddress((void**)&mn,    g_mn);
    cudaGetSymbolAddress((void**)&mx,    g_mx);

    // dynamic smem sizes (3 stages)
    const int SM00 = 3 * (ROWCH + COLCH) * 16;   // 56832
    const int SM10 = 3 * (COLCH + COLCH) * 16;   // 52224
    const int SM01 = 3 * (ROWCH + ROWCH) * 16;   // 61440
    cudaFuncSetAttribute(pgemm<0,0,1>, cudaFuncAttributeMaxDynamicSharedMemorySize, SM00);
    cudaFuncSetAttribute(pgemm<0,0,0>, cudaFuncAttributeMaxDynamicSharedMemorySize, SM00);
    cudaFuncSetAttribute(pgemm<1,0,1>, cudaFuncAttributeMaxDynamicSharedMemorySize, SM10);
    cudaFuncSetAttribute(pgemm<0,1,1>, cudaFuncAttributeMaxDynamicSharedMemorySize, SM01);
    cudaFuncSetAttribute(dualgemm,     cudaFuncAttributeMaxDynamicSharedMemorySize, SM00);

    // 0. weight conversion + LN + inv_freq
    f2h_kernel<<<((long long)DD*UVW + 255)/256, 256>>>(W1, W1h, (long long)DD*UVW);
    f2h_kernel<<<((long long)EE*DD  + 255)/256, 256>>>(W2, W2h, (long long)EE*DD);
    ln_kernel<<<TT, 256>>>(inputs, ln_w, ln_b, xn);
    invf_kernel<<<1, 64>>>(invf);

    // 2. uv = silu(xn @ W1 + b1)   [32768,768]x[768,3200] -> fp16
    pgemm<0,0,1><<<dim3(25, 256, 1), 256, SM00>>>(
        xn, W1h, uv, TT, UVW, DD, DD, UVW, UVW, 0, 0, 0,
        1.f, 1, b1, nullptr, 0);

    // 3. RoPE components
    rope_kernel<<<TT, 64>>>(uv, gamma, beta, invf, qq, qkk, lq, lk);

    // 4. kv[b] = lin_k[b]^T @ v[b]
    pgemm<1,0,1><<<dim3(12, 1, BB), 256, SM10>>>(
        lk, uv + EE, kv, SS, EE, GG*NN_, SS, UVW, EE,
        (long long)GG*NN_*SS, (long long)GG*NN_*UVW, (long long)SS*EE,
        1.f, 0, nullptr, nullptr, 0);

    // 5. lin_v[b] = lin_q[b] @ kv[b]
    pgemm<0,0,1><<<dim3(12, 32, BB), 256, SM00>>>(
        lq, kv, linv, GG*NN_, EE, SS, SS, EE, EE,
        (long long)GG*NN_*SS, (long long)SS*EE, (long long)GG*NN_*EE,
        1.f, 0, nullptr, nullptr, 0);

    // 6. lin_kv[bg] = lin_k[bg]^T @ lin_v[bg] / n
    pgemm<1,0,1><<<dim3(12, 1, BB*GG), 256, SM10>>>(
        lk, linv, linkv, SS, EE, NN_, SS, EE, EE,
        (long long)NN_*SS, (long long)NN_*EE, (long long)SS*EE,
        1.f / (float)NN_, 0, nullptr, nullptr, 0);

    // 7. segment mask mixing
    minmax_kernel<<<BB*GG, 256>>>(seg, mn, mx);
    mix_kernel<<<dim3((SS*EE)/256, BB), 256>>>(linkv, mn, mx, linkv2);

    // 9. qk[bg] = relu(quad_q@quad_k^T/n + toeplitz)^2 -> fp16 (epi=4)
    pgemm<0,1,1><<<dim3(2, 2, BB*GG), 256, SM01>>>(
        qq, qkk, qkm, NN_, NN_, SS, SS, SS, NN_,
        (long long)NN_*SS, (long long)NN_*SS, (long long)NN_*NN_,
        1.f / (float)NN_, 4, w_rel, nullptr, 0);

    // 8+10+11+12. gated = u * (lq@linkv2 + qkm@v)   (dual GEMM, fused gate)
    dualgemm<<<dim3(12, 2, BB*GG), 256, SM00>>>(lq, linkv2, qkm, uv, gated);

    // 13. out = gated @ W2 + b2 + shortcut -> fp32
    pgemm<0,0,0><<<dim3(6, 256, 1), 256, SM00>>>(
        gated, W2h, outp, TT, DD, EE, EE, DD, DD, 0, 0, 0,
        1.f, 2, b2, inputs, DD);
}